// round 1
// baseline (speedup 1.0000x reference)
#include <cuda_runtime.h>

#define B_  4
#define S_  2048
#define D_  1024
#define H_  16
#define DK_ 64

// Scratch (device globals: no allocations allowed)
__device__ float g_Q[(size_t)B_*H_*DK_*S_];   // [B,H,dk,S]  k-major
__device__ float g_K[(size_t)B_*H_*DK_*S_];   // [B,H,dk,S]  k-major
__device__ float g_V[(size_t)B_*H_*S_*DK_];   // [B,H,S,dv]
__device__ float g_X[(size_t)B_*S_*D_];       // concat-heads attention output

// ---------------------------------------------------------------------------
// QKV projection: emb[8192,1024] x W[h][1024,64] for z in {Q,K,V}
// 128x64 output tile, BK=16, 256 threads, 8x4 per-thread microtile.
// Q,K stored transposed (k-major) for the attention kernel; V stored natural.
// ---------------------------------------------------------------------------
__global__ __launch_bounds__(256) void proj_kernel(
    const float* __restrict__ emb, const float* __restrict__ Wq,
    const float* __restrict__ Wk,  const float* __restrict__ Wv)
{
    __shared__ __align__(16) float As[16][132];  // [k][m], padded
    __shared__ __align__(16) float Bs[16][64];   // [k][n]

    const int m0 = blockIdx.x * 128;
    const int h  = blockIdx.y;
    const int z  = blockIdx.z;
    const float* W = (z == 0 ? Wq : (z == 1 ? Wk : Wv)) + (size_t)h * D_ * DK_;

    const int tid = threadIdx.x;
    const int ty = tid >> 4, tx = tid & 15;

    float acc[8][4];
#pragma unroll
    for (int i = 0; i < 8; i++)
#pragma unroll
        for (int j = 0; j < 4; j++) acc[i][j] = 0.f;

    for (int k0 = 0; k0 < D_; k0 += 16) {
#pragma unroll
        for (int t = 0; t < 2; t++) {
            int i = tid + t * 256;
            int row = i >> 2, cv = i & 3;
            float4 v = *(const float4*)(emb + (size_t)(m0 + row) * D_ + k0 + cv * 4);
            As[cv*4+0][row] = v.x; As[cv*4+1][row] = v.y;
            As[cv*4+2][row] = v.z; As[cv*4+3][row] = v.w;
        }
        {
            int row = tid >> 4, cv = tid & 15;
            *(float4*)&Bs[row][cv*4] = *(const float4*)(W + (size_t)(k0 + row) * DK_ + cv * 4);
        }
        __syncthreads();
#pragma unroll
        for (int kk = 0; kk < 16; kk++) {
            float a[8], b[4];
            *(float4*)&a[0] = *(const float4*)&As[kk][ty*8];
            *(float4*)&a[4] = *(const float4*)&As[kk][ty*8+4];
            *(float4*)&b[0] = *(const float4*)&Bs[kk][tx*4];
#pragma unroll
            for (int i = 0; i < 8; i++)
#pragma unroll
                for (int j = 0; j < 4; j++) acc[i][j] += a[i] * b[j];
        }
        __syncthreads();
    }

    if (z < 2) {
        float* out = (z == 0) ? g_Q : g_K;
#pragma unroll
        for (int i = 0; i < 8; i++) {
            int m = m0 + ty*8 + i;
            int b = m / S_, s = m % S_;
            size_t base = ((size_t)(b * H_ + h) * DK_) * S_ + s;
#pragma unroll
            for (int j = 0; j < 4; j++)
                out[base + (size_t)(tx*4 + j) * S_] = acc[i][j];
        }
    } else {
#pragma unroll
        for (int i = 0; i < 8; i++) {
            int m = m0 + ty*8 + i;
            int b = m / S_, s = m % S_;
            float4 v = make_float4(acc[i][0], acc[i][1], acc[i][2], acc[i][3]);
            *(float4*)(g_V + ((size_t)(b * H_ + h) * S_ + s) * DK_ + tx*4) = v;
        }
    }
}

// ---------------------------------------------------------------------------
// Flash attention, causal. BQ=BK=64, dk=dv=64, 256 threads (16x16),
// each thread owns a 4x4 tile of scores/output. Q,K read k-major from global
// so SMEM copies are coalesced + conflict-free. Online softmax.
// ---------------------------------------------------------------------------
__global__ __launch_bounds__(256) void flash_kernel()
{
    extern __shared__ float sm[];
    float* Qst = sm;              // [k][r]  64x64
    float* Kst = sm + 64*64;      // [k][c]  64x64
    float* Vs  = sm + 2*64*64;    // [c][v]  64x64
    float* Ps  = sm + 3*64*64;    // [r][c]  64x64

    const int qt = blockIdx.x, h = blockIdx.y, b = blockIdx.z;
    const int bh = b * H_ + h;
    const float* Qb = g_Q + (size_t)bh * DK_ * S_;
    const float* Kb = g_K + (size_t)bh * DK_ * S_;
    const float* Vb = g_V + (size_t)bh * S_ * DK_;
    const int q0 = qt * 64;
    const int tid = threadIdx.x;
    const int ty = tid >> 4, tx = tid & 15;

#pragma unroll
    for (int t = 0; t < 4; t++) {
        int i = tid + t * 256;
        int k = i >> 4, rq = i & 15;
        *(float4*)(Qst + k*64 + rq*4) = *(const float4*)(Qb + (size_t)k * S_ + q0 + rq*4);
    }

    float m_i[4], l_i[4], o[4][4];
#pragma unroll
    for (int i = 0; i < 4; i++) {
        m_i[i] = -1e30f; l_i[i] = 0.f;
#pragma unroll
        for (int j = 0; j < 4; j++) o[i][j] = 0.f;
    }

    const int ntiles = qt + 1;   // causal: only tiles with kv <= q
    for (int kt = 0; kt < ntiles; ++kt) {
        const int kv0 = kt * 64;
        __syncthreads();
#pragma unroll
        for (int t = 0; t < 4; t++) {
            int i = tid + t * 256;
            int r = i >> 4, cq = i & 15;
            *(float4*)(Kst + r*64 + cq*4) = *(const float4*)(Kb + (size_t)r * S_ + kv0 + cq*4);
            *(float4*)(Vs  + r*64 + cq*4) = *(const float4*)(Vb + (size_t)(kv0 + r) * DK_ + cq*4);
        }
        __syncthreads();

        float sc[4][4];
#pragma unroll
        for (int i = 0; i < 4; i++)
#pragma unroll
            for (int j = 0; j < 4; j++) sc[i][j] = 0.f;

#pragma unroll 8
        for (int k = 0; k < 64; k++) {
            float qa[4], ka[4];
            *(float4*)qa = *(const float4*)(Qst + k*64 + ty*4);
            *(float4*)ka = *(const float4*)(Kst + k*64 + tx*4);
#pragma unroll
            for (int i = 0; i < 4; i++)
#pragma unroll
                for (int j = 0; j < 4; j++) sc[i][j] += qa[i] * ka[j];
        }

        const float scale = 0.125f;  // 1/sqrt(64)
#pragma unroll
        for (int i = 0; i < 4; i++)
#pragma unroll
            for (int j = 0; j < 4; j++) sc[i][j] *= scale;

        if (kt == qt) {  // diagonal tile: mask c > r (q0 == kv0)
#pragma unroll
            for (int i = 0; i < 4; i++)
#pragma unroll
                for (int j = 0; j < 4; j++)
                    if (tx*4 + j > ty*4 + i) sc[i][j] = -1e30f;
        }

#pragma unroll
        for (int i = 0; i < 4; i++) {
            float rm = fmaxf(fmaxf(sc[i][0], sc[i][1]), fmaxf(sc[i][2], sc[i][3]));
#pragma unroll
            for (int off = 1; off < 16; off <<= 1)
                rm = fmaxf(rm, __shfl_xor_sync(0xffffffffu, rm, off));
            float mnew = fmaxf(m_i[i], rm);
            float corr = __expf(m_i[i] - mnew);
            m_i[i] = mnew;
            float rs = 0.f;
#pragma unroll
            for (int j = 0; j < 4; j++) {
                float p = __expf(sc[i][j] - mnew);
                sc[i][j] = p; rs += p;
            }
#pragma unroll
            for (int off = 1; off < 16; off <<= 1)
                rs += __shfl_xor_sync(0xffffffffu, rs, off);
            l_i[i] = l_i[i] * corr + rs;
#pragma unroll
            for (int j = 0; j < 4; j++) o[i][j] *= corr;
            *(float4*)(Ps + (ty*4 + i)*64 + tx*4) =
                make_float4(sc[i][0], sc[i][1], sc[i][2], sc[i][3]);
        }
        __syncthreads();

#pragma unroll 4
        for (int c4 = 0; c4 < 16; c4++) {
            float pf[4][4], vf[4][4];
#pragma unroll
            for (int i = 0; i < 4; i++)
                *(float4*)pf[i] = *(const float4*)(Ps + (ty*4 + i)*64 + c4*4);
#pragma unroll
            for (int e = 0; e < 4; e++)
                *(float4*)vf[e] = *(const float4*)(Vs + (c4*4 + e)*64 + tx*4);
#pragma unroll
            for (int i = 0; i < 4; i++)
#pragma unroll
                for (int e = 0; e < 4; e++)
#pragma unroll
                    for (int j = 0; j < 4; j++)
                        o[i][j] += pf[i][e] * vf[e][j];
        }
    }

#pragma unroll
    for (int i = 0; i < 4; i++) {
        float inv = 1.f / l_i[i];
        int q = q0 + ty*4 + i;
        float4 v = make_float4(o[i][0]*inv, o[i][1]*inv, o[i][2]*inv, o[i][3]*inv);
        *(float4*)(g_X + ((size_t)b * S_ + q) * D_ + h * DK_ + tx*4) = v;
    }
}

// ---------------------------------------------------------------------------
// Output projection: g_X[8192,1024] x Wo[1024,1024] + bo
// ---------------------------------------------------------------------------
__global__ __launch_bounds__(256) void oproj_kernel(
    const float* __restrict__ Wo, const float* __restrict__ bo,
    float* __restrict__ out)
{
    __shared__ __align__(16) float As[16][132];
    __shared__ __align__(16) float Bs[16][64];

    const int m0 = blockIdx.x * 128;
    const int n0 = blockIdx.y * 64;
    const int tid = threadIdx.x;
    const int ty = tid >> 4, tx = tid & 15;

    float acc[8][4];
#pragma unroll
    for (int i = 0; i < 8; i++)
#pragma unroll
        for (int j = 0; j < 4; j++) acc[i][j] = 0.f;

    for (int k0 = 0; k0 < D_; k0 += 16) {
#pragma unroll
        for (int t = 0; t < 2; t++) {
            int i = tid + t * 256;
            int row = i >> 2, cv = i & 3;
            float4 v = *(const float4*)(g_X + (size_t)(m0 + row) * D_ + k0 + cv * 4);
            As[cv*4+0][row] = v.x; As[cv*4+1][row] = v.y;
            As[cv*4+2][row] = v.z; As[cv*4+3][row] = v.w;
        }
        {
            int row = tid >> 4, cv = tid & 15;
            *(float4*)&Bs[row][cv*4] =
                *(const float4*)(Wo + (size_t)(k0 + row) * D_ + n0 + cv * 4);
        }
        __syncthreads();
#pragma unroll
        for (int kk = 0; kk < 16; kk++) {
            float a[8], bfr[4];
            *(float4*)&a[0]   = *(const float4*)&As[kk][ty*8];
            *(float4*)&a[4]   = *(const float4*)&As[kk][ty*8+4];
            *(float4*)&bfr[0] = *(const float4*)&Bs[kk][tx*4];
#pragma unroll
            for (int i = 0; i < 8; i++)
#pragma unroll
                for (int j = 0; j < 4; j++) acc[i][j] += a[i] * bfr[j];
        }
        __syncthreads();
    }

    float bias[4];
    *(float4*)bias = *(const float4*)(bo + n0 + tx*4);
#pragma unroll
    for (int i = 0; i < 8; i++) {
        int m = m0 + ty*8 + i;
        float4 v = make_float4(acc[i][0]+bias[0], acc[i][1]+bias[1],
                               acc[i][2]+bias[2], acc[i][3]+bias[3]);
        *(float4*)(out + (size_t)m * D_ + n0 + tx*4) = v;
    }
}

// ---------------------------------------------------------------------------
extern "C" void kernel_launch(void* const* d_in, const int* in_sizes, int n_in,
                              void* d_out, int out_size)
{
    const float* emb = (const float*)d_in[0];
    const float* Wq  = (const float*)d_in[1];
    const float* Wk  = (const float*)d_in[2];
    const float* Wv  = (const float*)d_in[3];
    const float* Wo  = (const float*)d_in[4];
    const float* bo  = (const float*)d_in[5];
    float* out = (float*)d_out;

    cudaFuncSetAttribute(flash_kernel,
                         cudaFuncAttributeMaxDynamicSharedMemorySize, 65536);

    proj_kernel <<<dim3((B_*S_)/128, H_, 3), 256>>>(emb, Wq, Wk, Wv);
    flash_kernel<<<dim3(S_/64, H_, B_), 256, 65536>>>();
    oproj_kernel<<<dim3((B_*S_)/128, D_/64), 256>>>(Wo, bo, out);
}

// round 5
// speedup vs baseline: 1.4896x; 1.4896x over previous
#include <cuda_runtime.h>
#include <cstdint>

#define B_  4
#define S_  2048
#define D_  1024
#define H_  16
#define DK_ 64

#define QKV_Z ((size_t)B_*H_*DK_*S_)   // floats per z-slab

// Scratch (device globals: no allocations allowed).
// NOTE: these MUST only be referenced from device code (host-side references
// give the host shadow address, which GB300 ATS silently dereferences!).
__device__ float g_QKV[3*QKV_Z];              // z0: Q [B,H,dk,S]; z1: K [B,H,dk,S]; z2: V [B,H,S,dv]
__device__ float g_X[(size_t)B_*S_*D_];       // concat-heads attention output
__device__ float g_Wall[(size_t)3*H_*DK_*D_]; // [3072][1024] K-major fused QKV weights
__device__ float g_Wot[(size_t)D_*D_];        // [1024][1024] K-major output weights

// ============================ helpers ======================================
__device__ __forceinline__ uint32_t f2tf32(float x) {
    uint32_t u;
    asm("cvt.rna.tf32.f32 %0, %1;" : "=r"(u) : "f"(x));
    return u;
}
__device__ __forceinline__ void mma8(float* d, const uint32_t* a, const uint32_t* b) {
    asm volatile(
        "mma.sync.aligned.m16n8k8.row.col.f32.tf32.tf32.f32 "
        "{%0,%1,%2,%3}, {%4,%5,%6,%7}, {%8,%9}, {%0,%1,%2,%3};"
        : "+f"(d[0]), "+f"(d[1]), "+f"(d[2]), "+f"(d[3])
        : "r"(a[0]), "r"(a[1]), "r"(a[2]), "r"(a[3]), "r"(b[0]), "r"(b[1]));
}

// ====================== weight transposes (tiny) ===========================
__global__ __launch_bounds__(256) void wtrans_kernel(
    const float* __restrict__ Wq, const float* __restrict__ Wk,
    const float* __restrict__ Wv)
{
    __shared__ float t[64][65];
    const int dt = blockIdx.x, h = blockIdx.y, z = blockIdx.z;
    const float* W = (z == 0 ? Wq : (z == 1 ? Wk : Wv)) + (size_t)h * D_ * DK_;
    const int d0 = dt * 64;
#pragma unroll
    for (int i = 0; i < 16; i++) {
        int idx = threadIdx.x + i * 256;
        int r = idx >> 6, c = idx & 63;
        t[c][r] = W[(size_t)(d0 + r) * DK_ + c];
    }
    __syncthreads();
#pragma unroll
    for (int i = 0; i < 16; i++) {
        int idx = threadIdx.x + i * 256;
        int r = idx >> 6, c = idx & 63;
        g_Wall[(size_t)(z * 1024 + h * 64 + r) * D_ + d0 + c] = t[r][c];
    }
}

__global__ __launch_bounds__(256) void wot_kernel(const float* __restrict__ Wo)
{
    __shared__ float t[64][65];
    const int kt = blockIdx.x, nt = blockIdx.y;
    const int k0 = kt * 64, n0 = nt * 64;
#pragma unroll
    for (int i = 0; i < 16; i++) {
        int idx = threadIdx.x + i * 256;
        int r = idx >> 6, c = idx & 63;
        t[c][r] = Wo[(size_t)(k0 + r) * D_ + n0 + c];
    }
    __syncthreads();
#pragma unroll
    for (int i = 0; i < 16; i++) {
        int idx = threadIdx.x + i * 256;
        int r = idx >> 6, c = idx & 63;
        g_Wot[(size_t)(n0 + r) * D_ + k0 + c] = t[r][c];
    }
}

// =============== HMMA tf32 GEMM: C[M,N] = A[M,K] * B[N,K]^T ================
// 128x128 CTA tile, 8 warps as 4(M)x2(N) -> 32x64 warp tiles, KC=32 dbl-buf.
// mode 0: A = emb (arg), B = g_Wall; epilogue scatters into g_QKV.
// mode 1: A = g_X, B = g_Wot; epilogue adds bias, writes Cout (arg).
#define MMLDA 36
#define MM_SMEM_BYTES 73728

__global__ __launch_bounds__(256) void mm_kernel(
    const float* __restrict__ Aext, const float* __restrict__ bias,
    float* __restrict__ Cout, int mode)
{
    extern __shared__ __align__(16) uint32_t smu[];
    uint32_t* Asb[2] = { smu,        smu + 9216 };
    uint32_t* Bsb[2] = { smu + 4608, smu + 13824 };

    // device-side resolution of scratch globals (host must not pass them!)
    const float* A  = (mode == 0) ? Aext : g_X;
    const float* Bm = (mode == 0) ? g_Wall : g_Wot;

    const int tid = threadIdx.x;
    const int m0 = blockIdx.x * 128, n0 = blockIdx.y * 128;
    const int w = tid >> 5, lane = tid & 31;
    const int wm = w & 3, wn = w >> 2;
    const int g = lane >> 2, t = lane & 3;

    float acc[2][8][4];
#pragma unroll
    for (int mi = 0; mi < 2; mi++)
#pragma unroll
        for (int ni = 0; ni < 8; ni++)
#pragma unroll
            for (int r = 0; r < 4; r++) acc[mi][ni][r] = 0.f;

    const int ldr = tid >> 3, ldc = tid & 7;  // row step 32, col 8 float4s

    float4 ra[4], rb[4];
#pragma unroll
    for (int i = 0; i < 4; i++) {
        ra[i] = __ldg((const float4*)(A  + (size_t)(m0 + ldr + i * 32) * D_ + ldc * 4));
        rb[i] = __ldg((const float4*)(Bm + (size_t)(n0 + ldr + i * 32) * D_ + ldc * 4));
    }
#pragma unroll
    for (int i = 0; i < 4; i++) {
        uint32_t* pa = &Asb[0][(ldr + i * 32) * MMLDA + ldc * 4];
        pa[0] = f2tf32(ra[i].x); pa[1] = f2tf32(ra[i].y);
        pa[2] = f2tf32(ra[i].z); pa[3] = f2tf32(ra[i].w);
        uint32_t* pb = &Bsb[0][(ldr + i * 32) * MMLDA + ldc * 4];
        pb[0] = f2tf32(rb[i].x); pb[1] = f2tf32(rb[i].y);
        pb[2] = f2tf32(rb[i].z); pb[3] = f2tf32(rb[i].w);
    }
    __syncthreads();

    for (int c = 0; c < 32; c++) {
        const int cur = c & 1;
        if (c + 1 < 32) {
            const int k0n = (c + 1) * 32;
#pragma unroll
            for (int i = 0; i < 4; i++) {
                ra[i] = __ldg((const float4*)(A  + (size_t)(m0 + ldr + i * 32) * D_ + k0n + ldc * 4));
                rb[i] = __ldg((const float4*)(Bm + (size_t)(n0 + ldr + i * 32) * D_ + k0n + ldc * 4));
            }
        }
        const uint32_t* As = Asb[cur];
        const uint32_t* Bs = Bsb[cur];
#pragma unroll
        for (int ks = 0; ks < 4; ks++) {
            const int k = ks * 8;
            uint32_t af[2][4];
#pragma unroll
            for (int mi = 0; mi < 2; mi++) {
                int row = wm * 32 + mi * 16 + g;
                af[mi][0] = As[row * MMLDA + k + t];
                af[mi][1] = As[(row + 8) * MMLDA + k + t];
                af[mi][2] = As[row * MMLDA + k + t + 4];
                af[mi][3] = As[(row + 8) * MMLDA + k + t + 4];
            }
#pragma unroll
            for (int ni = 0; ni < 8; ni++) {
                int n = wn * 64 + ni * 8 + g;
                uint32_t bf[2] = { Bs[n * MMLDA + k + t], Bs[n * MMLDA + k + t + 4] };
                mma8(acc[0][ni], af[0], bf);
                mma8(acc[1][ni], af[1], bf);
            }
        }
        if (c + 1 < 32) {
            const int nxt = cur ^ 1;
#pragma unroll
            for (int i = 0; i < 4; i++) {
                uint32_t* pa = &Asb[nxt][(ldr + i * 32) * MMLDA + ldc * 4];
                pa[0] = f2tf32(ra[i].x); pa[1] = f2tf32(ra[i].y);
                pa[2] = f2tf32(ra[i].z); pa[3] = f2tf32(ra[i].w);
                uint32_t* pb = &Bsb[nxt][(ldr + i * 32) * MMLDA + ldc * 4];
                pb[0] = f2tf32(rb[i].x); pb[1] = f2tf32(rb[i].y);
                pb[2] = f2tf32(rb[i].z); pb[3] = f2tf32(rb[i].w);
            }
        }
        __syncthreads();
    }

    // ---------------- epilogue ----------------
    if (mode == 0) {
        const int z = n0 >> 10;                 // tile fully within one z
        const int bidx = m0 >> 11, s0 = m0 & 2047;
        if (z < 2) {
            // transpose via SMEM for coalesced k-major stores
            float* smf = (float*)smu;           // [col][row], ld=132
#pragma unroll
            for (int mi = 0; mi < 2; mi++)
#pragma unroll
                for (int ni = 0; ni < 8; ni++) {
                    int r = wm * 32 + mi * 16 + g;
                    int cc = wn * 64 + ni * 8 + 2 * t;
                    smf[cc * 132 + r]           = acc[mi][ni][0];
                    smf[(cc + 1) * 132 + r]     = acc[mi][ni][1];
                    smf[cc * 132 + r + 8]       = acc[mi][ni][2];
                    smf[(cc + 1) * 132 + r + 8] = acc[mi][ni][3];
                }
            __syncthreads();
            float* zbase = g_QKV + (size_t)z * QKV_Z;
#pragma unroll
            for (int ccc = 0; ccc < 16; ccc++) {
                int col = w + ccc * 8;
                int nglob = n0 + col;
                int h = (nglob >> 6) & 15, kb = nglob & 63;
                float* dst = zbase + ((size_t)(bidx * 16 + h) * 64 + kb) * 2048 + s0;
#pragma unroll
                for (int rr = 0; rr < 4; rr++)
                    dst[rr * 32 + lane] = smf[col * 132 + rr * 32 + lane];
            }
        } else {
            float* vbase = g_QKV + 2 * QKV_Z;
#pragma unroll
            for (int mi = 0; mi < 2; mi++)
#pragma unroll
                for (int ni = 0; ni < 8; ni++) {
                    int r = m0 + wm * 32 + mi * 16 + g;
                    int s = r & 2047;
                    int n = n0 + wn * 64 + ni * 8 + 2 * t;
                    int h = (n >> 6) & 15, kb = n & 63;
                    float* dst = vbase + ((size_t)(bidx * 16 + h) * 2048 + s) * 64 + kb;
                    *(float2*)dst = make_float2(acc[mi][ni][0], acc[mi][ni][1]);
                    *(float2*)(dst + 8 * 64) = make_float2(acc[mi][ni][2], acc[mi][ni][3]);
                }
        }
    } else {
#pragma unroll
        for (int mi = 0; mi < 2; mi++)
#pragma unroll
            for (int ni = 0; ni < 8; ni++) {
                int m = m0 + wm * 32 + mi * 16 + g;
                int n = n0 + wn * 64 + ni * 8 + 2 * t;
                float2 bv = *(const float2*)(bias + n);
                *(float2*)(Cout + (size_t)m * D_ + n) =
                    make_float2(acc[mi][ni][0] + bv.x, acc[mi][ni][1] + bv.y);
                *(float2*)(Cout + (size_t)(m + 8) * D_ + n) =
                    make_float2(acc[mi][ni][2] + bv.x, acc[mi][ni][3] + bv.y);
            }
    }
}

// ---------------------------------------------------------------------------
// Flash attention, causal fp32 SIMT (round-1 verified-correct version).
// BQ=BK=64, 256 threads (16x16), 4x4 per-thread tiles, online softmax.
// ---------------------------------------------------------------------------
__global__ __launch_bounds__(256) void flash_kernel()
{
    extern __shared__ float sm[];
    float* Qst = sm;              // [k][r]  64x64
    float* Kst = sm + 64*64;      // [k][c]  64x64
    float* Vs  = sm + 2*64*64;    // [c][v]  64x64
    float* Ps  = sm + 3*64*64;    // [r][c]  64x64

    const int qt = blockIdx.x, h = blockIdx.y, b = blockIdx.z;
    const int bh = b * H_ + h;
    const float* Qb = g_QKV + (size_t)bh * DK_ * S_;
    const float* Kb = g_QKV + QKV_Z + (size_t)bh * DK_ * S_;
    const float* Vb = g_QKV + 2 * QKV_Z + (size_t)bh * S_ * DK_;
    const int q0 = qt * 64;
    const int tid = threadIdx.x;
    const int ty = tid >> 4, tx = tid & 15;

#pragma unroll
    for (int t = 0; t < 4; t++) {
        int i = tid + t * 256;
        int k = i >> 4, rq = i & 15;
        *(float4*)(Qst + k*64 + rq*4) = *(const float4*)(Qb + (size_t)k * S_ + q0 + rq*4);
    }

    float m_i[4], l_i[4], o[4][4];
#pragma unroll
    for (int i = 0; i < 4; i++) {
        m_i[i] = -1e30f; l_i[i] = 0.f;
#pragma unroll
        for (int j = 0; j < 4; j++) o[i][j] = 0.f;
    }

    const int ntiles = qt + 1;
    for (int kt = 0; kt < ntiles; ++kt) {
        const int kv0 = kt * 64;
        __syncthreads();
#pragma unroll
        for (int t = 0; t < 4; t++) {
            int i = tid + t * 256;
            int r = i >> 4, cq = i & 15;
            *(float4*)(Kst + r*64 + cq*4) = *(const float4*)(Kb + (size_t)r * S_ + kv0 + cq*4);
            *(float4*)(Vs  + r*64 + cq*4) = *(const float4*)(Vb + (size_t)(kv0 + r) * DK_ + cq*4);
        }
        __syncthreads();

        float sc[4][4];
#pragma unroll
        for (int i = 0; i < 4; i++)
#pragma unroll
            for (int j = 0; j < 4; j++) sc[i][j] = 0.f;

#pragma unroll 8
        for (int k = 0; k < 64; k++) {
            float qa[4], ka[4];
            *(float4*)qa = *(const float4*)(Qst + k*64 + ty*4);
            *(float4*)ka = *(const float4*)(Kst + k*64 + tx*4);
#pragma unroll
            for (int i = 0; i < 4; i++)
#pragma unroll
                for (int j = 0; j < 4; j++) sc[i][j] += qa[i] * ka[j];
        }

        const float scale = 0.125f;
#pragma unroll
        for (int i = 0; i < 4; i++)
#pragma unroll
            for (int j = 0; j < 4; j++) sc[i][j] *= scale;

        if (kt == qt) {
#pragma unroll
            for (int i = 0; i < 4; i++)
#pragma unroll
                for (int j = 0; j < 4; j++)
                    if (tx*4 + j > ty*4 + i) sc[i][j] = -1e30f;
        }

#pragma unroll
        for (int i = 0; i < 4; i++) {
            float rm = fmaxf(fmaxf(sc[i][0], sc[i][1]), fmaxf(sc[i][2], sc[i][3]));
#pragma unroll
            for (int off = 1; off < 16; off <<= 1)
                rm = fmaxf(rm, __shfl_xor_sync(0xffffffffu, rm, off));
            float mnew = fmaxf(m_i[i], rm);
            float corr = __expf(m_i[i] - mnew);
            m_i[i] = mnew;
            float rs = 0.f;
#pragma unroll
            for (int j = 0; j < 4; j++) {
                float p = __expf(sc[i][j] - mnew);
                sc[i][j] = p; rs += p;
            }
#pragma unroll
            for (int off = 1; off < 16; off <<= 1)
                rs += __shfl_xor_sync(0xffffffffu, rs, off);
            l_i[i] = l_i[i] * corr + rs;
#pragma unroll
            for (int j = 0; j < 4; j++) o[i][j] *= corr;
            *(float4*)(Ps + (ty*4 + i)*64 + tx*4) =
                make_float4(sc[i][0], sc[i][1], sc[i][2], sc[i][3]);
        }
        __syncthreads();

#pragma unroll 4
        for (int c4 = 0; c4 < 16; c4++) {
            float pf[4][4], vf[4][4];
#pragma unroll
            for (int i = 0; i < 4; i++)
                *(float4*)pf[i] = *(const float4*)(Ps + (ty*4 + i)*64 + c4*4);
#pragma unroll
            for (int e = 0; e < 4; e++)
                *(float4*)vf[e] = *(const float4*)(Vs + (c4*4 + e)*64 + tx*4);
#pragma unroll
            for (int i = 0; i < 4; i++)
#pragma unroll
                for (int e = 0; e < 4; e++)
#pragma unroll
                    for (int j = 0; j < 4; j++)
                        o[i][j] += pf[i][e] * vf[e][j];
        }
    }

#pragma unroll
    for (int i = 0; i < 4; i++) {
        float inv = 1.f / l_i[i];
        int q = q0 + ty*4 + i;
        float4 v = make_float4(o[i][0]*inv, o[i][1]*inv, o[i][2]*inv, o[i][3]*inv);
        *(float4*)(g_X + ((size_t)b * S_ + q) * D_ + h * DK_ + tx*4) = v;
    }
}

// ---------------------------------------------------------------------------
extern "C" void kernel_launch(void* const* d_in, const int* in_sizes, int n_in,
                              void* d_out, int out_size)
{
    const float* emb = (const float*)d_in[0];
    const float* Wq  = (const float*)d_in[1];
    const float* Wk  = (const float*)d_in[2];
    const float* Wv  = (const float*)d_in[3];
    const float* Wo  = (const float*)d_in[4];
    const float* bo  = (const float*)d_in[5];
    float* out = (float*)d_out;

    cudaFuncSetAttribute(mm_kernel,
                         cudaFuncAttributeMaxDynamicSharedMemorySize, MM_SMEM_BYTES);
    cudaFuncSetAttribute(flash_kernel,
                         cudaFuncAttributeMaxDynamicSharedMemorySize, 65536);

    wtrans_kernel<<<dim3(16, 16, 3), 256>>>(Wq, Wk, Wv);
    wot_kernel   <<<dim3(16, 16), 256>>>(Wo);
    mm_kernel    <<<dim3(64, 24), 256, MM_SMEM_BYTES>>>(emb, nullptr, nullptr, 0);
    flash_kernel <<<dim3(S_/64, H_, B_), 256, 65536>>>();
    mm_kernel    <<<dim3(64, 8), 256, MM_SMEM_BYTES>>>(nullptr, bo, out, 1);
}

// round 6
// speedup vs baseline: 2.3577x; 1.5828x over previous
#include <cuda_runtime.h>
#include <cstdint>

#define B_  4
#define S_  2048
#define D_  1024
#define H_  16
#define DK_ 64

#define QKV_Z ((size_t)B_*H_*DK_*S_)   // floats per z-slab

// Scratch (device globals). MUST only be referenced from device code:
// host-side references give the host shadow address, which GB300 ATS
// silently dereferences (round-3/4 bug).
__device__ float g_QKV[3*QKV_Z];              // z0: Q [B,H,dk,S]; z1: K [B,H,dk,S]; z2: V [B,H,S,dv]
__device__ float g_X[(size_t)B_*S_*D_];       // concat-heads attention output
__device__ float g_Wall[(size_t)3*H_*DK_*D_]; // [3072][1024] K-major fused QKV weights
__device__ float g_Wot[(size_t)D_*D_];        // [1024][1024] K-major output weights

// ============================ helpers ======================================
__device__ __forceinline__ uint32_t f2tf32(float x) {
    uint32_t u;
    asm("cvt.rna.tf32.f32 %0, %1;" : "=r"(u) : "f"(x));
    return u;
}
__device__ __forceinline__ void mma8(float* d, const uint32_t* a, const uint32_t* b) {
    asm volatile(
        "mma.sync.aligned.m16n8k8.row.col.f32.tf32.tf32.f32 "
        "{%0,%1,%2,%3}, {%4,%5,%6,%7}, {%8,%9}, {%0,%1,%2,%3};"
        : "+f"(d[0]), "+f"(d[1]), "+f"(d[2]), "+f"(d[3])
        : "r"(a[0]), "r"(a[1]), "r"(a[2]), "r"(a[3]), "r"(b[0]), "r"(b[1]));
}

// ====================== weight transposes (tiny) ===========================
__global__ __launch_bounds__(256) void wtrans_kernel(
    const float* __restrict__ Wq, const float* __restrict__ Wk,
    const float* __restrict__ Wv)
{
    __shared__ float t[64][65];
    const int dt = blockIdx.x, h = blockIdx.y, z = blockIdx.z;
    const float* W = (z == 0 ? Wq : (z == 1 ? Wk : Wv)) + (size_t)h * D_ * DK_;
    const int d0 = dt * 64;
#pragma unroll
    for (int i = 0; i < 16; i++) {
        int idx = threadIdx.x + i * 256;
        int r = idx >> 6, c = idx & 63;
        t[c][r] = W[(size_t)(d0 + r) * DK_ + c];
    }
    __syncthreads();
#pragma unroll
    for (int i = 0; i < 16; i++) {
        int idx = threadIdx.x + i * 256;
        int r = idx >> 6, c = idx & 63;
        g_Wall[(size_t)(z * 1024 + h * 64 + r) * D_ + d0 + c] = t[r][c];
    }
}

__global__ __launch_bounds__(256) void wot_kernel(const float* __restrict__ Wo)
{
    __shared__ float t[64][65];
    const int kt = blockIdx.x, nt = blockIdx.y;
    const int k0 = kt * 64, n0 = nt * 64;
#pragma unroll
    for (int i = 0; i < 16; i++) {
        int idx = threadIdx.x + i * 256;
        int r = idx >> 6, c = idx & 63;
        t[c][r] = Wo[(size_t)(k0 + r) * D_ + n0 + c];
    }
    __syncthreads();
#pragma unroll
    for (int i = 0; i < 16; i++) {
        int idx = threadIdx.x + i * 256;
        int r = idx >> 6, c = idx & 63;
        g_Wot[(size_t)(n0 + r) * D_ + k0 + c] = t[r][c];
    }
}

// =============== HMMA tf32 GEMM: C[M,N] = A[M,K] * B[N,K]^T ================
// 128x128 CTA tile, 8 warps as 4(M)x2(N) -> 32x64 warp tiles, KC=32 dbl-buf.
// mode 0: A = emb (arg), B = g_Wall; epilogue scatters into g_QKV.
// mode 1: A = g_X, B = g_Wot; epilogue adds bias, writes Cout (arg).
#define MMLDA 36
#define MM_SMEM_BYTES 73728

__global__ __launch_bounds__(256) void mm_kernel(
    const float* __restrict__ Aext, const float* __restrict__ bias,
    float* __restrict__ Cout, int mode)
{
    extern __shared__ __align__(16) uint32_t smu[];
    uint32_t* Asb[2] = { smu,        smu + 9216 };
    uint32_t* Bsb[2] = { smu + 4608, smu + 13824 };

    const float* A  = (mode == 0) ? Aext : g_X;
    const float* Bm = (mode == 0) ? g_Wall : g_Wot;

    const int tid = threadIdx.x;
    const int m0 = blockIdx.x * 128, n0 = blockIdx.y * 128;
    const int w = tid >> 5, lane = tid & 31;
    const int wm = w & 3, wn = w >> 2;
    const int g = lane >> 2, t = lane & 3;

    float acc[2][8][4];
#pragma unroll
    for (int mi = 0; mi < 2; mi++)
#pragma unroll
        for (int ni = 0; ni < 8; ni++)
#pragma unroll
            for (int r = 0; r < 4; r++) acc[mi][ni][r] = 0.f;

    const int ldr = tid >> 3, ldc = tid & 7;

    float4 ra[4], rb[4];
#pragma unroll
    for (int i = 0; i < 4; i++) {
        ra[i] = __ldg((const float4*)(A  + (size_t)(m0 + ldr + i * 32) * D_ + ldc * 4));
        rb[i] = __ldg((const float4*)(Bm + (size_t)(n0 + ldr + i * 32) * D_ + ldc * 4));
    }
#pragma unroll
    for (int i = 0; i < 4; i++) {
        uint32_t* pa = &Asb[0][(ldr + i * 32) * MMLDA + ldc * 4];
        pa[0] = f2tf32(ra[i].x); pa[1] = f2tf32(ra[i].y);
        pa[2] = f2tf32(ra[i].z); pa[3] = f2tf32(ra[i].w);
        uint32_t* pb = &Bsb[0][(ldr + i * 32) * MMLDA + ldc * 4];
        pb[0] = f2tf32(rb[i].x); pb[1] = f2tf32(rb[i].y);
        pb[2] = f2tf32(rb[i].z); pb[3] = f2tf32(rb[i].w);
    }
    __syncthreads();

    for (int c = 0; c < 32; c++) {
        const int cur = c & 1;
        if (c + 1 < 32) {
            const int k0n = (c + 1) * 32;
#pragma unroll
            for (int i = 0; i < 4; i++) {
                ra[i] = __ldg((const float4*)(A  + (size_t)(m0 + ldr + i * 32) * D_ + k0n + ldc * 4));
                rb[i] = __ldg((const float4*)(Bm + (size_t)(n0 + ldr + i * 32) * D_ + k0n + ldc * 4));
            }
        }
        const uint32_t* As = Asb[cur];
        const uint32_t* Bs = Bsb[cur];
#pragma unroll
        for (int ks = 0; ks < 4; ks++) {
            const int k = ks * 8;
            uint32_t af[2][4];
#pragma unroll
            for (int mi = 0; mi < 2; mi++) {
                int row = wm * 32 + mi * 16 + g;
                af[mi][0] = As[row * MMLDA + k + t];
                af[mi][1] = As[(row + 8) * MMLDA + k + t];
                af[mi][2] = As[row * MMLDA + k + t + 4];
                af[mi][3] = As[(row + 8) * MMLDA + k + t + 4];
            }
#pragma unroll
            for (int ni = 0; ni < 8; ni++) {
                int n = wn * 64 + ni * 8 + g;
                uint32_t bf[2] = { Bs[n * MMLDA + k + t], Bs[n * MMLDA + k + t + 4] };
                mma8(acc[0][ni], af[0], bf);
                mma8(acc[1][ni], af[1], bf);
            }
        }
        if (c + 1 < 32) {
            const int nxt = cur ^ 1;
#pragma unroll
            for (int i = 0; i < 4; i++) {
                uint32_t* pa = &Asb[nxt][(ldr + i * 32) * MMLDA + ldc * 4];
                pa[0] = f2tf32(ra[i].x); pa[1] = f2tf32(ra[i].y);
                pa[2] = f2tf32(ra[i].z); pa[3] = f2tf32(ra[i].w);
                uint32_t* pb = &Bsb[nxt][(ldr + i * 32) * MMLDA + ldc * 4];
                pb[0] = f2tf32(rb[i].x); pb[1] = f2tf32(rb[i].y);
                pb[2] = f2tf32(rb[i].z); pb[3] = f2tf32(rb[i].w);
            }
        }
        __syncthreads();
    }

    // ---------------- epilogue ----------------
    if (mode == 0) {
        const int z = n0 >> 10;
        const int bidx = m0 >> 11, s0 = m0 & 2047;
        if (z < 2) {
            float* smf = (float*)smu;           // [col][row], ld=132
#pragma unroll
            for (int mi = 0; mi < 2; mi++)
#pragma unroll
                for (int ni = 0; ni < 8; ni++) {
                    int r = wm * 32 + mi * 16 + g;
                    int cc = wn * 64 + ni * 8 + 2 * t;
                    smf[cc * 132 + r]           = acc[mi][ni][0];
                    smf[(cc + 1) * 132 + r]     = acc[mi][ni][1];
                    smf[cc * 132 + r + 8]       = acc[mi][ni][2];
                    smf[(cc + 1) * 132 + r + 8] = acc[mi][ni][3];
                }
            __syncthreads();
            float* zbase = g_QKV + (size_t)z * QKV_Z;
#pragma unroll
            for (int ccc = 0; ccc < 16; ccc++) {
                int col = w + ccc * 8;
                int nglob = n0 + col;
                int h = (nglob >> 6) & 15, kb = nglob & 63;
                float* dst = zbase + ((size_t)(bidx * 16 + h) * 64 + kb) * 2048 + s0;
#pragma unroll
                for (int rr = 0; rr < 4; rr++)
                    dst[rr * 32 + lane] = smf[col * 132 + rr * 32 + lane];
            }
        } else {
            float* vbase = g_QKV + 2 * QKV_Z;
#pragma unroll
            for (int mi = 0; mi < 2; mi++)
#pragma unroll
                for (int ni = 0; ni < 8; ni++) {
                    int r = m0 + wm * 32 + mi * 16 + g;
                    int s = r & 2047;
                    int n = n0 + wn * 64 + ni * 8 + 2 * t;
                    int h = (n >> 6) & 15, kb = n & 63;
                    float* dst = vbase + ((size_t)(bidx * 16 + h) * 2048 + s) * 64 + kb;
                    *(float2*)dst = make_float2(acc[mi][ni][0], acc[mi][ni][1]);
                    *(float2*)(dst + 8 * 64) = make_float2(acc[mi][ni][2], acc[mi][ni][3]);
                }
        }
    } else {
#pragma unroll
        for (int mi = 0; mi < 2; mi++)
#pragma unroll
            for (int ni = 0; ni < 8; ni++) {
                int m = m0 + wm * 32 + mi * 16 + g;
                int n = n0 + wn * 64 + ni * 8 + 2 * t;
                float2 bv = *(const float2*)(bias + n);
                *(float2*)(Cout + (size_t)m * D_ + n) =
                    make_float2(acc[mi][ni][0] + bv.x, acc[mi][ni][1] + bv.y);
                *(float2*)(Cout + (size_t)(m + 8) * D_ + n) =
                    make_float2(acc[mi][ni][2] + bv.x, acc[mi][ni][3] + bv.y);
            }
    }
}

// ================ Flash attention on HMMA tf32, causal =====================
// BQ=128, BK=64, 256 threads; warp wq owns q-rows [wq*16, wq*16+16).
// Qs [64k][136] tf32 (pre-scaled by 1/8), Ks [64k][72], Vs [64kv][72].
#define FL_QS   0
#define FL_KS   8704
#define FL_VS   13312
#define FL_SMEM_BYTES 71680

__global__ __launch_bounds__(256) void flash_kernel()
{
    extern __shared__ __align__(16) uint32_t smu[];
    uint32_t* Qs = smu + FL_QS;
    uint32_t* Ks = smu + FL_KS;
    uint32_t* Vs = smu + FL_VS;

    const int qt = blockIdx.x, h = blockIdx.y, b = blockIdx.z;
    const int bh = b * H_ + h;
    const float* Qb = g_QKV + (size_t)bh * DK_ * S_;
    const float* Kb = g_QKV + QKV_Z + (size_t)bh * DK_ * S_;
    const float* Vb = g_QKV + 2 * QKV_Z + (size_t)bh * S_ * DK_;
    const int q0 = qt * 128;
    const int tid = threadIdx.x;
    const int wq = tid >> 5, lane = tid & 31;
    const int g = lane >> 2, t = lane & 3;
    const int qb = wq * 16;

    // load Q (scaled by 1/8, tf32) -> Qs[k][q], ld=136
#pragma unroll
    for (int i = 0; i < 8; i++) {
        int idx = tid + i * 256;
        int k = idx >> 5, q4 = idx & 31;
        float4 v = __ldg((const float4*)(Qb + (size_t)k * S_ + q0 + q4 * 4));
        uint32_t* p = &Qs[k * 136 + q4 * 4];
        p[0] = f2tf32(v.x * 0.125f); p[1] = f2tf32(v.y * 0.125f);
        p[2] = f2tf32(v.z * 0.125f); p[3] = f2tf32(v.w * 0.125f);
    }

    float m_i[2] = { -1e30f, -1e30f }, l_i[2] = { 0.f, 0.f };
    float accO[8][4];
#pragma unroll
    for (int ni = 0; ni < 8; ni++)
#pragma unroll
        for (int r = 0; r < 4; r++) accO[ni][r] = 0.f;

    const int ntiles = 2 * qt + 2;
    for (int kt = 0; kt < ntiles; kt++) {
        const int kv0 = kt * 64;
        __syncthreads();
#pragma unroll
        for (int i = 0; i < 4; i++) {
            int idx = tid + i * 256;
            int r = idx >> 4, c4 = idx & 15;
            float4 kv = __ldg((const float4*)(Kb + (size_t)r * S_ + kv0 + c4 * 4));
            uint32_t* pk = &Ks[r * 72 + c4 * 4];
            pk[0] = f2tf32(kv.x); pk[1] = f2tf32(kv.y);
            pk[2] = f2tf32(kv.z); pk[3] = f2tf32(kv.w);
            float4 vv = __ldg((const float4*)(Vb + (size_t)(kv0 + r) * DK_ + c4 * 4));
            uint32_t* pv = &Vs[r * 72 + c4 * 4];
            pv[0] = f2tf32(vv.x); pv[1] = f2tf32(vv.y);
            pv[2] = f2tf32(vv.z); pv[3] = f2tf32(vv.w);
        }
        __syncthreads();

        // S = Q K^T  (warp: 16 x 64)
        float sf[8][4];
#pragma unroll
        for (int ni = 0; ni < 8; ni++)
#pragma unroll
            for (int r = 0; r < 4; r++) sf[ni][r] = 0.f;

#pragma unroll
        for (int ks = 0; ks < 8; ks++) {
            const int k = ks * 8;
            uint32_t af[4];
            af[0] = Qs[(k + t) * 136 + qb + g];
            af[1] = Qs[(k + t) * 136 + qb + g + 8];
            af[2] = Qs[(k + t + 4) * 136 + qb + g];
            af[3] = Qs[(k + t + 4) * 136 + qb + g + 8];
#pragma unroll
            for (int ni = 0; ni < 8; ni++) {
                uint32_t bf[2] = { Ks[(k + t) * 72 + ni * 8 + g],
                                   Ks[(k + t + 4) * 72 + ni * 8 + g] };
                mma8(sf[ni], af, bf);
            }
        }

        if (kt >= 2 * qt) {  // diagonal region: apply causal mask
            const int qr0 = q0 + qb + g, qr1 = qr0 + 8;
#pragma unroll
            for (int ni = 0; ni < 8; ni++) {
                int c0 = kv0 + ni * 8 + 2 * t;
                if (c0     > qr0) sf[ni][0] = -1e30f;
                if (c0 + 1 > qr0) sf[ni][1] = -1e30f;
                if (c0     > qr1) sf[ni][2] = -1e30f;
                if (c0 + 1 > qr1) sf[ni][3] = -1e30f;
            }
        }

        // online softmax: row halves rh=0 (regs 0,1 -> q=qb+g), rh=1 (regs 2,3)
#pragma unroll
        for (int rh = 0; rh < 2; rh++) {
            float mx = -1e30f;
#pragma unroll
            for (int ni = 0; ni < 8; ni++)
                mx = fmaxf(mx, fmaxf(sf[ni][rh * 2], sf[ni][rh * 2 + 1]));
            mx = fmaxf(mx, __shfl_xor_sync(0xffffffffu, mx, 1));
            mx = fmaxf(mx, __shfl_xor_sync(0xffffffffu, mx, 2));
            float mnew = fmaxf(m_i[rh], mx);
            float corr = __expf(m_i[rh] - mnew);
            m_i[rh] = mnew;
            float sum = 0.f;
#pragma unroll
            for (int ni = 0; ni < 8; ni++) {
                float p0 = __expf(sf[ni][rh * 2] - mnew);
                float p1 = __expf(sf[ni][rh * 2 + 1] - mnew);
                sum += p0 + p1;
                sf[ni][rh * 2]     = __uint_as_float(f2tf32(p0));
                sf[ni][rh * 2 + 1] = __uint_as_float(f2tf32(p1));
            }
            sum += __shfl_xor_sync(0xffffffffu, sum, 1);
            sum += __shfl_xor_sync(0xffffffffu, sum, 2);
            l_i[rh] = l_i[rh] * corr + sum;
#pragma unroll
            for (int ni = 0; ni < 8; ni++) {
                accO[ni][rh * 2]     *= corr;
                accO[ni][rh * 2 + 1] *= corr;
            }
        }

        // O += P V : re-fragment P via width-4 shuffles
        const int tt = t >> 1, tt2 = tt + 2;
        const bool hi = (t & 1);
#pragma unroll
        for (int kj = 0; kj < 8; kj++) {
            uint32_t af[4];
            {
                float v0 = __shfl_sync(0xffffffffu, sf[kj][0], tt, 4);
                float v1 = __shfl_sync(0xffffffffu, sf[kj][1], tt, 4);
                af[0] = __float_as_uint(hi ? v1 : v0);
                float v2 = __shfl_sync(0xffffffffu, sf[kj][2], tt, 4);
                float v3 = __shfl_sync(0xffffffffu, sf[kj][3], tt, 4);
                af[1] = __float_as_uint(hi ? v3 : v2);
                float u0 = __shfl_sync(0xffffffffu, sf[kj][0], tt2, 4);
                float u1 = __shfl_sync(0xffffffffu, sf[kj][1], tt2, 4);
                af[2] = __float_as_uint(hi ? u1 : u0);
                float u2 = __shfl_sync(0xffffffffu, sf[kj][2], tt2, 4);
                float u3 = __shfl_sync(0xffffffffu, sf[kj][3], tt2, 4);
                af[3] = __float_as_uint(hi ? u3 : u2);
            }
            const int k = kj * 8;
#pragma unroll
            for (int ni = 0; ni < 8; ni++) {
                uint32_t bf[2] = { Vs[(k + t) * 72 + ni * 8 + g],
                                   Vs[(k + t + 4) * 72 + ni * 8 + g] };
                mma8(accO[ni], af, bf);
            }
        }
    }

    // write O -> g_X [b][q][h*64 + dv]
    const float inv0 = 1.f / l_i[0], inv1 = 1.f / l_i[1];
    const int q = q0 + qb + g;
    float* xb = g_X + ((size_t)b * S_ + q) * D_ + h * DK_;
#pragma unroll
    for (int ni = 0; ni < 8; ni++) {
        int dv = ni * 8 + 2 * t;
        *(float2*)(xb + dv) = make_float2(accO[ni][0] * inv0, accO[ni][1] * inv0);
        *(float2*)(xb + 8 * D_ + dv) = make_float2(accO[ni][2] * inv1, accO[ni][3] * inv1);
    }
}

// ---------------------------------------------------------------------------
extern "C" void kernel_launch(void* const* d_in, const int* in_sizes, int n_in,
                              void* d_out, int out_size)
{
    const float* emb = (const float*)d_in[0];
    const float* Wq  = (const float*)d_in[1];
    const float* Wk  = (const float*)d_in[2];
    const float* Wv  = (const float*)d_in[3];
    const float* Wo  = (const float*)d_in[4];
    const float* bo  = (const float*)d_in[5];
    float* out = (float*)d_out;

    cudaFuncSetAttribute(mm_kernel,
                         cudaFuncAttributeMaxDynamicSharedMemorySize, MM_SMEM_BYTES);
    cudaFuncSetAttribute(flash_kernel,
                         cudaFuncAttributeMaxDynamicSharedMemorySize, FL_SMEM_BYTES);

    wtrans_kernel<<<dim3(16, 16, 3), 256>>>(Wq, Wk, Wv);
    wot_kernel   <<<dim3(16, 16), 256>>>(Wo);
    mm_kernel    <<<dim3(64, 24), 256, MM_SMEM_BYTES>>>(emb, nullptr, nullptr, 0);
    flash_kernel <<<dim3(S_/128, H_, B_), 256, FL_SMEM_BYTES>>>();
    mm_kernel    <<<dim3(64, 8), 256, MM_SMEM_BYTES>>>(nullptr, bo, out, 1);
}

// round 7
// speedup vs baseline: 2.6025x; 1.1038x over previous
#include <cuda_runtime.h>
#include <cstdint>

#define B_  4
#define S_  2048
#define D_  1024
#define H_  16
#define DK_ 64

#define QKV_Z ((size_t)B_*H_*DK_*S_)   // floats per z-slab

// Scratch (device globals). MUST only be referenced from device code:
// host-side references give the host shadow address, which GB300 ATS
// silently dereferences (round-3/4 bug).
__device__ float g_QKV[3*QKV_Z];              // z0: Q [B,H,dk,S] (tf32, pre-scaled 1/8); z1: K (tf32); z2: V [B,H,S,dv] (tf32)
__device__ float g_X[(size_t)B_*S_*D_];       // concat-heads attention output
__device__ float g_Wall[(size_t)3*H_*DK_*D_]; // [3072][1024] K-major fused QKV weights (tf32)
__device__ float g_Wot[(size_t)D_*D_];        // [1024][1024] K-major output weights (tf32)

// ============================ helpers ======================================
__device__ __forceinline__ uint32_t f2tf32(float x) {
    uint32_t u;
    asm("cvt.rna.tf32.f32 %0, %1;" : "=r"(u) : "f"(x));
    return u;
}
__device__ __forceinline__ void mma8(float* d, const uint32_t* a, const uint32_t* b) {
    asm volatile(
        "mma.sync.aligned.m16n8k8.row.col.f32.tf32.tf32.f32 "
        "{%0,%1,%2,%3}, {%4,%5,%6,%7}, {%8,%9}, {%0,%1,%2,%3};"
        : "+f"(d[0]), "+f"(d[1]), "+f"(d[2]), "+f"(d[3])
        : "r"(a[0]), "r"(a[1]), "r"(a[2]), "r"(a[3]), "r"(b[0]), "r"(b[1]));
}
__device__ __forceinline__ uint32_t smem_u32(const void* p) {
    uint32_t a;
    asm("{ .reg .u64 t; cvta.to.shared.u64 t, %1; cvt.u32.u64 %0, t; }"
        : "=r"(a) : "l"(p));
    return a;
}
#define CP16(d, s) \
    asm volatile("cp.async.cg.shared.global [%0], [%1], 16;" :: "r"(d), "l"(s))
#define CP_COMMIT() asm volatile("cp.async.commit_group;" ::: "memory")
#define CP_WAIT0()  asm volatile("cp.async.wait_group 0;" ::: "memory")
#define CP_WAIT1()  asm volatile("cp.async.wait_group 1;" ::: "memory")

// ====================== weight transposes (tiny, pre-convert tf32) ========
__global__ __launch_bounds__(256) void wtrans_kernel(
    const float* __restrict__ Wq, const float* __restrict__ Wk,
    const float* __restrict__ Wv)
{
    __shared__ float t[64][65];
    const int dt = blockIdx.x, h = blockIdx.y, z = blockIdx.z;
    const float* W = (z == 0 ? Wq : (z == 1 ? Wk : Wv)) + (size_t)h * D_ * DK_;
    const int d0 = dt * 64;
#pragma unroll
    for (int i = 0; i < 16; i++) {
        int idx = threadIdx.x + i * 256;
        int r = idx >> 6, c = idx & 63;
        t[c][r] = W[(size_t)(d0 + r) * DK_ + c];
    }
    __syncthreads();
#pragma unroll
    for (int i = 0; i < 16; i++) {
        int idx = threadIdx.x + i * 256;
        int r = idx >> 6, c = idx & 63;
        g_Wall[(size_t)(z * 1024 + h * 64 + r) * D_ + d0 + c] =
            __uint_as_float(f2tf32(t[r][c]));
    }
}

__global__ __launch_bounds__(256) void wot_kernel(const float* __restrict__ Wo)
{
    __shared__ float t[64][65];
    const int kt = blockIdx.x, nt = blockIdx.y;
    const int k0 = kt * 64, n0 = nt * 64;
#pragma unroll
    for (int i = 0; i < 16; i++) {
        int idx = threadIdx.x + i * 256;
        int r = idx >> 6, c = idx & 63;
        t[c][r] = Wo[(size_t)(k0 + r) * D_ + n0 + c];
    }
    __syncthreads();
#pragma unroll
    for (int i = 0; i < 16; i++) {
        int idx = threadIdx.x + i * 256;
        int r = idx >> 6, c = idx & 63;
        g_Wot[(size_t)(n0 + r) * D_ + k0 + c] = __uint_as_float(f2tf32(t[r][c]));
    }
}

// =============== HMMA tf32 GEMM: C[M,N] = A[M,K] * B[N,K]^T ================
// 128x128 CTA tile, 8 warps as 4(M)x2(N) -> 32x64 warp tiles, KC=32 dbl-buf.
// B side arrives pre-converted tf32 -> cp.async straight to smem.
// mode 0: A = emb (arg, fp32), B = g_Wall; epilogue scatters tf32 Q/K/V.
// mode 1: A = g_X (fp32), B = g_Wot; epilogue adds bias, writes Cout (arg).
#define MMLDA 36
#define MM_SMEM_BYTES 73728

__global__ __launch_bounds__(256) void mm_kernel(
    const float* __restrict__ Aext, const float* __restrict__ bias,
    float* __restrict__ Cout, int mode)
{
    extern __shared__ __align__(16) uint32_t smu[];
    uint32_t* Asb[2] = { smu,        smu + 9216 };
    uint32_t* Bsb[2] = { smu + 4608, smu + 13824 };
    const uint32_t sb = smem_u32(smu);
    const uint32_t Bsa[2] = { sb + 4608u * 4u, sb + 13824u * 4u };

    const float* A  = (mode == 0) ? Aext : g_X;
    const float* Bm = (mode == 0) ? g_Wall : g_Wot;

    const int tid = threadIdx.x;
    const int m0 = blockIdx.x * 128, n0 = blockIdx.y * 128;
    const int w = tid >> 5, lane = tid & 31;
    const int wm = w & 3, wn = w >> 2;
    const int g = lane >> 2, t = lane & 3;

    float acc[2][8][4];
#pragma unroll
    for (int mi = 0; mi < 2; mi++)
#pragma unroll
        for (int ni = 0; ni < 8; ni++)
#pragma unroll
            for (int r = 0; r < 4; r++) acc[mi][ni][r] = 0.f;

    const int ldr = tid >> 3, ldc = tid & 7;
    const uint32_t dsto = (uint32_t)(ldr * MMLDA + ldc * 4) * 4u;

    // ---- prologue: chunk 0 ----
#pragma unroll
    for (int i = 0; i < 4; i++)
        CP16(Bsa[0] + dsto + (uint32_t)(i * 32 * MMLDA * 4),
             Bm + (size_t)(n0 + ldr + i * 32) * D_ + ldc * 4);
    CP_COMMIT();
    {
        float4 ra[4];
#pragma unroll
        for (int i = 0; i < 4; i++)
            ra[i] = __ldg((const float4*)(A + (size_t)(m0 + ldr + i * 32) * D_ + ldc * 4));
#pragma unroll
        for (int i = 0; i < 4; i++) {
            uint32_t* pa = &Asb[0][(ldr + i * 32) * MMLDA + ldc * 4];
            pa[0] = f2tf32(ra[i].x); pa[1] = f2tf32(ra[i].y);
            pa[2] = f2tf32(ra[i].z); pa[3] = f2tf32(ra[i].w);
        }
    }
    CP_WAIT0();
    __syncthreads();

    for (int c = 0; c < 32; c++) {
        const int cur = c & 1;
        float4 ra[4];
        if (c + 1 < 32) {
            const int k0n = (c + 1) * 32;
#pragma unroll
            for (int i = 0; i < 4; i++)
                CP16(Bsa[cur ^ 1] + dsto + (uint32_t)(i * 32 * MMLDA * 4),
                     Bm + (size_t)(n0 + ldr + i * 32) * D_ + k0n + ldc * 4);
            CP_COMMIT();
#pragma unroll
            for (int i = 0; i < 4; i++)
                ra[i] = __ldg((const float4*)(A + (size_t)(m0 + ldr + i * 32) * D_ + k0n + ldc * 4));
        }
        const uint32_t* As = Asb[cur];
        const uint32_t* Bs = Bsb[cur];
#pragma unroll
        for (int ks = 0; ks < 4; ks++) {
            const int k = ks * 8;
            uint32_t af[2][4];
#pragma unroll
            for (int mi = 0; mi < 2; mi++) {
                int row = wm * 32 + mi * 16 + g;
                af[mi][0] = As[row * MMLDA + k + t];
                af[mi][1] = As[(row + 8) * MMLDA + k + t];
                af[mi][2] = As[row * MMLDA + k + t + 4];
                af[mi][3] = As[(row + 8) * MMLDA + k + t + 4];
            }
#pragma unroll
            for (int ni = 0; ni < 8; ni++) {
                int n = wn * 64 + ni * 8 + g;
                uint32_t bf[2] = { Bs[n * MMLDA + k + t], Bs[n * MMLDA + k + t + 4] };
                mma8(acc[0][ni], af[0], bf);
                mma8(acc[1][ni], af[1], bf);
            }
        }
        if (c + 1 < 32) {
            const int nxt = cur ^ 1;
#pragma unroll
            for (int i = 0; i < 4; i++) {
                uint32_t* pa = &Asb[nxt][(ldr + i * 32) * MMLDA + ldc * 4];
                pa[0] = f2tf32(ra[i].x); pa[1] = f2tf32(ra[i].y);
                pa[2] = f2tf32(ra[i].z); pa[3] = f2tf32(ra[i].w);
            }
        }
        CP_WAIT0();
        __syncthreads();
    }

    // ---------------- epilogue ----------------
    if (mode == 0) {
        const int z = n0 >> 10;
        const int bidx = m0 >> 11, s0 = m0 & 2047;
        if (z < 2) {
            const float qsc = (z == 0) ? 0.125f : 1.0f;
            float* smf = (float*)smu;           // [col][row], ld=132
#pragma unroll
            for (int mi = 0; mi < 2; mi++)
#pragma unroll
                for (int ni = 0; ni < 8; ni++) {
                    int r = wm * 32 + mi * 16 + g;
                    int cc = wn * 64 + ni * 8 + 2 * t;
                    smf[cc * 132 + r]           = acc[mi][ni][0];
                    smf[(cc + 1) * 132 + r]     = acc[mi][ni][1];
                    smf[cc * 132 + r + 8]       = acc[mi][ni][2];
                    smf[(cc + 1) * 132 + r + 8] = acc[mi][ni][3];
                }
            __syncthreads();
            float* zbase = g_QKV + (size_t)z * QKV_Z;
#pragma unroll
            for (int ccc = 0; ccc < 16; ccc++) {
                int col = w + ccc * 8;
                int nglob = n0 + col;
                int h = (nglob >> 6) & 15, kb = nglob & 63;
                float* dst = zbase + ((size_t)(bidx * 16 + h) * 64 + kb) * 2048 + s0;
#pragma unroll
                for (int rr = 0; rr < 4; rr++)
                    dst[rr * 32 + lane] =
                        __uint_as_float(f2tf32(qsc * smf[col * 132 + rr * 32 + lane]));
            }
        } else {
            float* vbase = g_QKV + 2 * QKV_Z;
#pragma unroll
            for (int mi = 0; mi < 2; mi++)
#pragma unroll
                for (int ni = 0; ni < 8; ni++) {
                    int r = m0 + wm * 32 + mi * 16 + g;
                    int s = r & 2047;
                    int n = n0 + wn * 64 + ni * 8 + 2 * t;
                    int h = (n >> 6) & 15, kb = n & 63;
                    float* dst = vbase + ((size_t)(bidx * 16 + h) * 2048 + s) * 64 + kb;
                    *(float2*)dst = make_float2(
                        __uint_as_float(f2tf32(acc[mi][ni][0])),
                        __uint_as_float(f2tf32(acc[mi][ni][1])));
                    *(float2*)(dst + 8 * 64) = make_float2(
                        __uint_as_float(f2tf32(acc[mi][ni][2])),
                        __uint_as_float(f2tf32(acc[mi][ni][3])));
                }
        }
    } else {
#pragma unroll
        for (int mi = 0; mi < 2; mi++)
#pragma unroll
            for (int ni = 0; ni < 8; ni++) {
                int m = m0 + wm * 32 + mi * 16 + g;
                int n = n0 + wn * 64 + ni * 8 + 2 * t;
                float2 bv = *(const float2*)(bias + n);
                *(float2*)(Cout + (size_t)m * D_ + n) =
                    make_float2(acc[mi][ni][0] + bv.x, acc[mi][ni][1] + bv.y);
                *(float2*)(Cout + (size_t)(m + 8) * D_ + n) =
                    make_float2(acc[mi][ni][2] + bv.x, acc[mi][ni][3] + bv.y);
            }
    }
}

// ================ Flash attention on HMMA tf32, causal =====================
// BQ=128, BK=64, 256 threads; warp wq owns q-rows [wq*16, wq*16+16).
// Q/K/V arrive pre-converted tf32 (Q pre-scaled 1/8) -> cp.async raw copies.
// Qs [64k][136]; K/V double-buffered [64][72] each.
#define FL_QS     0
#define FL_KS0    8704
#define FL_KS1    13312
#define FL_VS0    17920
#define FL_VS1    22528
#define FL_SMEM_BYTES 108544

__global__ __launch_bounds__(256) void flash_kernel()
{
    extern __shared__ __align__(16) uint32_t smu[];
    uint32_t* Qs = smu + FL_QS;
    const uint32_t sb = smem_u32(smu);
    const uint32_t Ksa[2] = { sb + FL_KS0 * 4u, sb + FL_KS1 * 4u };
    const uint32_t Vsa[2] = { sb + FL_VS0 * 4u, sb + FL_VS1 * 4u };
    uint32_t* Ksp[2] = { smu + FL_KS0, smu + FL_KS1 };
    uint32_t* Vsp[2] = { smu + FL_VS0, smu + FL_VS1 };

    const int qt = (int)gridDim.x - 1 - (int)blockIdx.x;  // heavy tiles first
    const int h = blockIdx.y, b = blockIdx.z;
    const int bh = b * H_ + h;
    const float* Qb = g_QKV + (size_t)bh * DK_ * S_;
    const float* Kb = g_QKV + QKV_Z + (size_t)bh * DK_ * S_;
    const float* Vb = g_QKV + 2 * QKV_Z + (size_t)bh * S_ * DK_;
    const int q0 = qt * 128;
    const int tid = threadIdx.x;
    const int wq = tid >> 5, lane = tid & 31;
    const int g = lane >> 2, t = lane & 3;
    const int qb = wq * 16;

    const int kvr = tid >> 4, kvc = (tid & 15) * 4;       // K/V copy coords
    const uint32_t kv_dst = (uint32_t)(kvr * 72 + kvc) * 4u;

    // prologue: Q (8x16B) + KV tile 0 (8x16B) in group 0
#pragma unroll
    for (int i = 0; i < 8; i++) {
        int idx = tid + i * 256;
        int k = idx >> 5, q4 = idx & 31;
        CP16(sb + (uint32_t)(k * 136 + q4 * 4) * 4u,
             Qb + (size_t)k * S_ + q0 + q4 * 4);
    }
#pragma unroll
    for (int i = 0; i < 4; i++) {
        int r = kvr + i * 16;
        CP16(Ksa[0] + kv_dst + (uint32_t)(i * 16 * 72 * 4), Kb + (size_t)r * S_ + kvc);
        CP16(Vsa[0] + kv_dst + (uint32_t)(i * 16 * 72 * 4), Vb + (size_t)r * DK_ + kvc);
    }
    CP_COMMIT();

    float m_i[2] = { -1e30f, -1e30f }, l_i[2] = { 0.f, 0.f };
    float accO[8][4];
#pragma unroll
    for (int ni = 0; ni < 8; ni++)
#pragma unroll
        for (int r = 0; r < 4; r++) accO[ni][r] = 0.f;

    const int ntiles = 2 * qt + 2;
    for (int kt = 0; kt < ntiles; kt++) {
        const int cur = kt & 1;
        if (kt + 1 < ntiles) {
            const int kv0n = (kt + 1) * 64;
#pragma unroll
            for (int i = 0; i < 4; i++) {
                int r = kvr + i * 16;
                CP16(Ksa[cur ^ 1] + kv_dst + (uint32_t)(i * 16 * 72 * 4),
                     Kb + (size_t)r * S_ + kv0n + kvc);
                CP16(Vsa[cur ^ 1] + kv_dst + (uint32_t)(i * 16 * 72 * 4),
                     Vb + (size_t)(kv0n + r) * DK_ + kvc);
            }
            CP_COMMIT();
            CP_WAIT1();
        } else {
            CP_WAIT0();
        }
        __syncthreads();

        const uint32_t* Ks = Ksp[cur];
        const uint32_t* Vs = Vsp[cur];

        // S = Q K^T  (warp: 16 x 64)
        float sf[8][4];
#pragma unroll
        for (int ni = 0; ni < 8; ni++)
#pragma unroll
            for (int r = 0; r < 4; r++) sf[ni][r] = 0.f;

#pragma unroll
        for (int ks = 0; ks < 8; ks++) {
            const int k = ks * 8;
            uint32_t af[4];
            af[0] = Qs[(k + t) * 136 + qb + g];
            af[1] = Qs[(k + t) * 136 + qb + g + 8];
            af[2] = Qs[(k + t + 4) * 136 + qb + g];
            af[3] = Qs[(k + t + 4) * 136 + qb + g + 8];
#pragma unroll
            for (int ni = 0; ni < 8; ni++) {
                uint32_t bf[2] = { Ks[(k + t) * 72 + ni * 8 + g],
                                   Ks[(k + t + 4) * 72 + ni * 8 + g] };
                mma8(sf[ni], af, bf);
            }
        }

        if (kt >= 2 * qt) {  // diagonal region: apply causal mask
            const int kv0 = kt * 64;
            const int qr0 = q0 + qb + g, qr1 = qr0 + 8;
#pragma unroll
            for (int ni = 0; ni < 8; ni++) {
                int c0 = kv0 + ni * 8 + 2 * t;
                if (c0     > qr0) sf[ni][0] = -1e30f;
                if (c0 + 1 > qr0) sf[ni][1] = -1e30f;
                if (c0     > qr1) sf[ni][2] = -1e30f;
                if (c0 + 1 > qr1) sf[ni][3] = -1e30f;
            }
        }

        // online softmax: rh=0 -> regs 0,1 (q=qb+g); rh=1 -> regs 2,3 (q+8)
#pragma unroll
        for (int rh = 0; rh < 2; rh++) {
            float mx = -1e30f;
#pragma unroll
            for (int ni = 0; ni < 8; ni++)
                mx = fmaxf(mx, fmaxf(sf[ni][rh * 2], sf[ni][rh * 2 + 1]));
            mx = fmaxf(mx, __shfl_xor_sync(0xffffffffu, mx, 1));
            mx = fmaxf(mx, __shfl_xor_sync(0xffffffffu, mx, 2));
            float mnew = fmaxf(m_i[rh], mx);
            float corr = __expf(m_i[rh] - mnew);
            m_i[rh] = mnew;
            float sum = 0.f;
#pragma unroll
            for (int ni = 0; ni < 8; ni++) {
                float p0 = __expf(sf[ni][rh * 2] - mnew);
                float p1 = __expf(sf[ni][rh * 2 + 1] - mnew);
                sum += p0 + p1;
                sf[ni][rh * 2]     = __uint_as_float(f2tf32(p0));
                sf[ni][rh * 2 + 1] = __uint_as_float(f2tf32(p1));
            }
            sum += __shfl_xor_sync(0xffffffffu, sum, 1);
            sum += __shfl_xor_sync(0xffffffffu, sum, 2);
            l_i[rh] = l_i[rh] * corr + sum;
#pragma unroll
            for (int ni = 0; ni < 8; ni++) {
                accO[ni][rh * 2]     *= corr;
                accO[ni][rh * 2 + 1] *= corr;
            }
        }

        // O += P V : re-fragment P via width-4 shuffles
        const int tt = t >> 1, tt2 = tt + 2;
        const bool hi = (t & 1);
#pragma unroll
        for (int kj = 0; kj < 8; kj++) {
            uint32_t af[4];
            {
                float v0 = __shfl_sync(0xffffffffu, sf[kj][0], tt, 4);
                float v1 = __shfl_sync(0xffffffffu, sf[kj][1], tt, 4);
                af[0] = __float_as_uint(hi ? v1 : v0);
                float v2 = __shfl_sync(0xffffffffu, sf[kj][2], tt, 4);
                float v3 = __shfl_sync(0xffffffffu, sf[kj][3], tt, 4);
                af[1] = __float_as_uint(hi ? v3 : v2);
                float u0 = __shfl_sync(0xffffffffu, sf[kj][0], tt2, 4);
                float u1 = __shfl_sync(0xffffffffu, sf[kj][1], tt2, 4);
                af[2] = __float_as_uint(hi ? u1 : u0);
                float u2 = __shfl_sync(0xffffffffu, sf[kj][2], tt2, 4);
                float u3 = __shfl_sync(0xffffffffu, sf[kj][3], tt2, 4);
                af[3] = __float_as_uint(hi ? u3 : u2);
            }
            const int k = kj * 8;
#pragma unroll
            for (int ni = 0; ni < 8; ni++) {
                uint32_t bf[2] = { Vs[(k + t) * 72 + ni * 8 + g],
                                   Vs[(k + t + 4) * 72 + ni * 8 + g] };
                mma8(accO[ni], af, bf);
            }
        }
        __syncthreads();
    }

    // write O -> g_X [b][q][h*64 + dv]
    const float inv0 = 1.f / l_i[0], inv1 = 1.f / l_i[1];
    const int q = q0 + qb + g;
    float* xb = g_X + ((size_t)b * S_ + q) * D_ + h * DK_;
#pragma unroll
    for (int ni = 0; ni < 8; ni++) {
        int dv = ni * 8 + 2 * t;
        *(float2*)(xb + dv) = make_float2(accO[ni][0] * inv0, accO[ni][1] * inv0);
        *(float2*)(xb + 8 * D_ + dv) = make_float2(accO[ni][2] * inv1, accO[ni][3] * inv1);
    }
}

// ---------------------------------------------------------------------------
extern "C" void kernel_launch(void* const* d_in, const int* in_sizes, int n_in,
                              void* d_out, int out_size)
{
    const float* emb = (const float*)d_in[0];
    const float* Wq  = (const float*)d_in[1];
    const float* Wk  = (const float*)d_in[2];
    const float* Wv  = (const float*)d_in[3];
    const float* Wo  = (const float*)d_in[4];
    const float* bo  = (const float*)d_in[5];
    float* out = (float*)d_out;

    cudaFuncSetAttribute(mm_kernel,
                         cudaFuncAttributeMaxDynamicSharedMemorySize, MM_SMEM_BYTES);
    cudaFuncSetAttribute(flash_kernel,
                         cudaFuncAttributeMaxDynamicSharedMemorySize, FL_SMEM_BYTES);

    wtrans_kernel<<<dim3(16, 16, 3), 256>>>(Wq, Wk, Wv);
    wot_kernel   <<<dim3(16, 16), 256>>>(Wo);
    mm_kernel    <<<dim3(64, 24), 256, MM_SMEM_BYTES>>>(emb, nullptr, nullptr, 0);
    flash_kernel <<<dim3(S_/128, H_, B_), 256, FL_SMEM_BYTES>>>();
    mm_kernel    <<<dim3(64, 8), 256, MM_SMEM_BYTES>>>(nullptr, bo, out, 1);
}